// round 16
// baseline (speedup 1.0000x reference)
#include <cuda_runtime.h>
#include <cuda_fp16.h>
#include <cstdint>
#include <math.h>

#define D_MODEL 2048
#define N_HEADS 16
#define HEAD_DIM 128
#define SEQ 2048
#define BATCH 2
#define M_ROWS (BATCH * SEQ)
#define BH (BATCH * N_HEADS)

// ---------------------------------------------------------------------------
// Scratch (static device arrays; no allocation at kernel_launch time)
// ---------------------------------------------------------------------------
__device__ __half g_x_hi[(size_t)M_ROWS * D_MODEL];
__device__ __half g_x_lo[(size_t)M_ROWS * D_MODEL];
__device__ __half g_a_hi[(size_t)M_ROWS * D_MODEL];
__device__ __half g_wq_h[(size_t)D_MODEL * D_MODEL];
__device__ __half g_wk_h[(size_t)D_MODEL * D_MODEL];
__device__ __half g_wv_h[(size_t)D_MODEL * D_MODEL];
__device__ __half g_wo_h[(size_t)D_MODEL * D_MODEL];
__device__ __half g_q16h[(size_t)BH * SEQ * HEAD_DIM];
__device__ __half g_q16l[(size_t)BH * SEQ * HEAD_DIM];
__device__ __half g_k16h[(size_t)BH * SEQ * HEAD_DIM];
__device__ __half g_k16l[(size_t)BH * SEQ * HEAD_DIM];
__device__ __half g_v16h[(size_t)BH * SEQ * HEAD_DIM];
__device__ __half g_vt16h[(size_t)BH * HEAD_DIM * SEQ];
__device__ float g_ropec[SEQ * 64];
__device__ float g_ropes[SEQ * 64];

// ---------------------------------------------------------------------------
// primitives
// ---------------------------------------------------------------------------
__device__ __forceinline__ uint32_t smem_u32(const void* p) {
    uint32_t a;
    asm("{ .reg .u64 t; cvta.to.shared.u64 t, %1; cvt.u32.u64 %0, t; }"
        : "=r"(a) : "l"(p));
    return a;
}
__device__ __forceinline__ void cp16(uint32_t s, const void* g) {
    asm volatile("cp.async.cg.shared.global [%0], [%1], 16;"
                 :: "r"(s), "l"(__cvta_generic_to_global(g)) : "memory");
}
#define CPC() asm volatile("cp.async.commit_group;" ::: "memory")
#define CPW(N) asm volatile("cp.async.wait_group %0;" :: "n"(N) : "memory")

#define LDSM4(r0, r1, r2, r3, addr)                                            \
    asm volatile("ldmatrix.sync.aligned.m8n8.x4.shared.b16 {%0,%1,%2,%3}, [%4];" \
                 : "=r"(r0), "=r"(r1), "=r"(r2), "=r"(r3) : "r"(addr))

__device__ __forceinline__ void mma16816(float* d, const uint32_t* a,
                                         const uint32_t* b) {
    asm volatile(
        "mma.sync.aligned.m16n8k16.row.col.f32.f16.f16.f32 "
        "{%0,%1,%2,%3}, {%4,%5,%6,%7}, {%8,%9}, {%0,%1,%2,%3};"
        : "+f"(d[0]), "+f"(d[1]), "+f"(d[2]), "+f"(d[3])
        : "r"(a[0]), "r"(a[1]), "r"(a[2]), "r"(a[3]), "r"(b[0]), "r"(b[1]));
}

// swizzles
__device__ __forceinline__ uint32_t g128(int r, int c) {  // r<128, c<8
    return (uint32_t)((r << 7) + ((c ^ (r & 7)) << 4));
}
__device__ __forceinline__ uint32_t qsw(int r, int c) {   // r<64, c<16
    return (uint32_t)((r << 8) + ((c ^ (r & 7)) << 4));
}
__device__ __forceinline__ uint32_t vsw(int r, int c) {   // r<128, c<8
    return (uint32_t)((r << 7) + ((c ^ (r & 7)) << 4));
}

__device__ __forceinline__ void split_h2(float a, float b, __half2& h, __half2& l)
{
    const __half h0 = __float2half(a), h1 = __float2half(b);
    h = __halves2half2(h0, h1);
    l = __halves2half2(__float2half(a - __half2float(h0)),
                       __float2half(b - __half2float(h1)));
}

// ---------------------------------------------------------------------------
// converts + RoPE tables
// ---------------------------------------------------------------------------
__global__ void mha_split16(const float* __restrict__ src,
                            __half* __restrict__ hi,
                            __half* __restrict__ lo, int n4)
{
    int i = blockIdx.x * blockDim.x + threadIdx.x;
    if (i >= n4) return;
    float4 v = ((const float4*)src)[i];
    __half2 h0, l0, h1, l1;
    split_h2(v.x, v.y, h0, l0);
    split_h2(v.z, v.w, h1, l1);
    ((__half2*)hi)[i * 2 + 0] = h0;
    ((__half2*)hi)[i * 2 + 1] = h1;
    ((__half2*)lo)[i * 2 + 0] = l0;
    ((__half2*)lo)[i * 2 + 1] = l1;
}

// 4 weight tensors in one launch (blockIdx.y selects)
__global__ void mha_cvt16x4(const float* __restrict__ s0, __half* __restrict__ d0,
                            const float* __restrict__ s1, __half* __restrict__ d1,
                            const float* __restrict__ s2, __half* __restrict__ d2,
                            const float* __restrict__ s3, __half* __restrict__ d3,
                            int n4)
{
    int i = blockIdx.x * blockDim.x + threadIdx.x;
    if (i >= n4) return;
    const float* src = (blockIdx.y == 0) ? s0 : (blockIdx.y == 1) ? s1
                       : (blockIdx.y == 2) ? s2 : s3;
    __half* dst = (blockIdx.y == 0) ? d0 : (blockIdx.y == 1) ? d1
                  : (blockIdx.y == 2) ? d2 : d3;
    float4 v = ((const float4*)src)[i];
    __half2* D = (__half2*)dst;
    D[i * 2 + 0] = __floats2half2_rn(v.x, v.y);
    D[i * 2 + 1] = __floats2half2_rn(v.z, v.w);
}

__global__ void mha_rope_tables(float* __restrict__ rc, float* __restrict__ rs)
{
    const int s = blockIdx.x;
    const int i = threadIdx.x;  // 0..63
    const int jc = (2 * i) & 63;
    const int js = (2 * i + 1) & 63;
    const float invc = powf(10000.0f, -(float)jc * (1.0f / 64.0f));
    const float invs = powf(10000.0f, -(float)js * (1.0f / 64.0f));
    rc[s * 64 + i] = cosf((float)s * invc);
    rs[s * 64 + i] = sinf((float)s * invs);
}

// ---------------------------------------------------------------------------
// Templated GEMM (unchanged from R15): tile 128x128, K-chunk 64, 4 warps
// 64x64 each, double-buffered cp.async.
// ---------------------------------------------------------------------------
#define GSTAGE 49152
#define GSMEM  (2 * GSTAGE)

template <int MODE, int NPASS>
__global__ __launch_bounds__(128, 2)
void gemm_t(const __half* __restrict__ Ahi, const __half* __restrict__ Alo,
            const __half* __restrict__ Bh, float* __restrict__ C,
            __half* __restrict__ OH, __half* __restrict__ OL, float scale,
            const float* __restrict__ rc, const float* __restrict__ rs,
            const __half* __restrict__ B2, __half* __restrict__ OH2,
            __half* __restrict__ OL2, float scale2)
{
    extern __shared__ char smg[];
    const uint32_t sbase = smem_u32(smg);
    const int K = D_MODEL;
    const int tid  = threadIdx.x;
    const int lane = tid & 31;
    const int wid  = tid >> 5;
    const int warp_m = wid & 1;
    const int warp_n = wid >> 1;
    const int m0 = blockIdx.y * 128;

    const __half* Bsel = Bh;
    __half* OHs = OH;
    __half* OLs = OL;
    float scl = scale;
    int nblk = blockIdx.x;
    if (MODE == 1 && nblk >= 16) {
        Bsel = B2; OHs = OH2; OLs = OL2; scl = scale2; nblk -= 16;
    }
    const int n0 = nblk * 128;

    float acc[4][8][4];
#pragma unroll
    for (int mt = 0; mt < 4; ++mt)
#pragma unroll
        for (int nt = 0; nt < 8; ++nt)
#pragma unroll
            for (int e = 0; e < 4; ++e) acc[mt][nt][e] = 0.f;

    auto load_chunk = [&](int kc, int s) {
        const uint32_t st = sbase + s * GSTAGE;
#pragma unroll
        for (int i = 0; i < 8; ++i) {
            const int idx = tid + i * 128;
            const int r = idx >> 3;
            const int c = idx & 7;
            const uint32_t so = g128(r, c);
            const size_t ga = (size_t)(m0 + r) * K + kc + c * 8;
            const size_t gb = (size_t)(n0 + r) * K + kc + c * 8;
            cp16(st + so, Ahi + ga);
            if (NPASS == 2) cp16(st + 16384 + so, Alo + ga);
            cp16(st + 32768 + so, Bsel + gb);
        }
    };

    load_chunk(0, 0);
    CPC();

    const int nchunks = K / 64;
    for (int c = 0; c < nchunks; ++c) {
        const int buf = c & 1;
        if (c + 1 < nchunks) {
            load_chunk((c + 1) * 64, buf ^ 1);
            CPC();
            CPW(1);
        } else {
            CPW(0);
        }
        __syncthreads();

        const uint32_t ab_hi = sbase + buf * GSTAGE;
        const uint32_t ab_lo = ab_hi + 16384;
        const uint32_t bb_hi = ab_hi + 32768;

#pragma unroll
        for (int ks = 0; ks < 4; ++ks) {
            const int ch = ks * 2 + (lane >> 4);
            uint32_t ah[4][4], al[4][4];
#pragma unroll
            for (int mt = 0; mt < 4; ++mt) {
                const int r = warp_m * 64 + mt * 16 + (lane & 15);
                const uint32_t so = g128(r, ch);
                LDSM4(ah[mt][0], ah[mt][1], ah[mt][2], ah[mt][3], ab_hi + so);
                if (NPASS == 2)
                    LDSM4(al[mt][0], al[mt][1], al[mt][2], al[mt][3], ab_lo + so);
            }
            uint32_t bh[8][2];
#pragma unroll
            for (int nt2 = 0; nt2 < 4; ++nt2) {
                const int r = warp_n * 64 + nt2 * 16 + (lane & 15);
                const uint32_t so = g128(r, ch);
                uint32_t t0, t1, t2, t3;
                LDSM4(t0, t1, t2, t3, bb_hi + so);
                bh[nt2 * 2][0] = t0; bh[nt2 * 2][1] = t2;
                bh[nt2 * 2 + 1][0] = t1; bh[nt2 * 2 + 1][1] = t3;
            }
#pragma unroll
            for (int nt = 0; nt < 8; ++nt)
#pragma unroll
                for (int mt = 0; mt < 4; ++mt)
                    mma16816(acc[mt][nt], ah[mt], bh[nt]);
            if (NPASS == 2) {
#pragma unroll
                for (int nt = 0; nt < 8; ++nt)
#pragma unroll
                    for (int mt = 0; mt < 4; ++mt)
                        mma16816(acc[mt][nt], al[mt], bh[nt]);
            }
        }
        __syncthreads();
    }

    // --- epilogue ---
#pragma unroll
    for (int mt = 0; mt < 4; ++mt) {
#pragma unroll
        for (int half = 0; half < 2; ++half) {
            const int row = m0 + warp_m * 64 + mt * 16 + (lane >> 2) + half * 8;
#pragma unroll
            for (int nt = 0; nt < 8; ++nt) {
                const int col = n0 + warp_n * 64 + nt * 8 + (lane & 3) * 2;
                float v0 = acc[mt][nt][half * 2 + 0];
                float v1 = acc[mt][nt][half * 2 + 1];
                if (MODE == 0) {
                    *(float2*)&C[(size_t)row * D_MODEL + col] = make_float2(v0, v1);
                } else {
                    const int s  = row & (SEQ - 1);
                    const int b  = row >> 11;
                    const int hh = col >> 7;
                    const int dd = col & (HEAD_DIM - 1);
                    const size_t idx =
                        (((size_t)(b * N_HEADS + hh)) * SEQ + s) * HEAD_DIM + dd;
                    if (MODE == 1) {
                        const float cc = rc[s * 64 + (dd >> 1)];
                        const float sn = rs[s * 64 + (dd >> 1)];
                        const float r1 = (v0 * cc - v1 * sn) * scl;
                        const float r2 = (v0 * sn + v1 * cc) * scl;
                        __half2 h, l;
                        split_h2(r1, r2, h, l);
                        *(__half2*)&OHs[idx] = h;
                        *(__half2*)&OLs[idx] = l;
                    } else {  // MODE == 2: hi only
                        *(__half2*)&OHs[idx] = __floats2half2_rn(v0, v1);
                    }
                }
            }
        }
    }
}

// ---------------------------------------------------------------------------
// fp16 transpose (hi only): [bh][s][d] -> [bh][d][s]
// ---------------------------------------------------------------------------
__global__ void mha_t16(const __half* __restrict__ vh, __half* __restrict__ vth)
{
    __shared__ __half t[32][33];
    const int bh = blockIdx.z;
    const int s0 = blockIdx.x * 32;
    const int d0 = blockIdx.y * 32;
    const int tx = threadIdx.x, ty = threadIdx.y;  // (32, 8)
    const size_t ib = (size_t)bh * SEQ * HEAD_DIM;
#pragma unroll
    for (int i = 0; i < 4; ++i)
        t[ty + 8 * i][tx] = vh[ib + (size_t)(s0 + ty + 8 * i) * HEAD_DIM + d0 + tx];
    __syncthreads();
    const size_t ob = (size_t)bh * HEAD_DIM * SEQ;
#pragma unroll
    for (int i = 0; i < 4; ++i) {
        const int d = d0 + ty + 8 * i;
        vth[ob + (size_t)d * SEQ + s0 + tx] = t[tx][ty + 8 * i];
    }
}

// ---------------------------------------------------------------------------
// Tensor-core causal flash attention. QK^T 3-pass (logit path), PV 1-pass.
// R16: Q fragments hoisted to registers (loop-invariant); longest-first CTA
// order (qb = gridDim.x-1-blockIdx.x) to fix causal load imbalance.
// ---------------------------------------------------------------------------
#define FA_SQH 0
#define FA_SQL 16384
#define FA_SKH 32768
#define FA_SKL 49152
#define FA_SVH 65536
#define FA_SMEM 81920

__global__ __launch_bounds__(128, 2)
void mha_flash_mma(const __half* __restrict__ qh, const __half* __restrict__ ql,
                   const __half* __restrict__ kh, const __half* __restrict__ kl,
                   const __half* __restrict__ vth, __half* __restrict__ AH)
{
    extern __shared__ char smfa[];
    const uint32_t sb = smem_u32(smfa);
    const int tid  = threadIdx.x;
    const int lane = tid & 31;
    const int w    = tid >> 5;
    const int qb   = gridDim.x - 1 - blockIdx.x;  // longest-first scheduling
    const int bh   = blockIdx.y;
    const int q0   = qb * 64;

    const size_t qoff = ((size_t)bh * SEQ + q0) * HEAD_DIM;
    const __half* Qh = qh + qoff;
    const __half* Ql = ql + qoff;
    const __half* Kb_h = kh + (size_t)bh * SEQ * HEAD_DIM;
    const __half* Kb_l = kl + (size_t)bh * SEQ * HEAD_DIM;
    const __half* Vb_h = vth + (size_t)bh * HEAD_DIM * SEQ;

#pragma unroll
    for (int i = 0; i < 8; ++i) {
        const int idx = tid + i * 128;
        const int r = idx >> 4;
        const int c = idx & 15;
        cp16(sb + FA_SQH + qsw(r, c), Qh + (size_t)r * HEAD_DIM + c * 8);
        cp16(sb + FA_SQL + qsw(r, c), Ql + (size_t)r * HEAD_DIM + c * 8);
    }
    CPC();
    CPW(0);
    __syncthreads();

    // hoist Q fragments (loop-invariant across kb)
    uint32_t qfh[8][4], qfl[8][4];
#pragma unroll
    for (int ks = 0; ks < 8; ++ks) {
        const int ch = ks * 2 + (lane >> 4);
        const uint32_t so = qsw(16 * w + (lane & 15), ch);
        LDSM4(qfh[ks][0], qfh[ks][1], qfh[ks][2], qfh[ks][3], sb + FA_SQH + so);
        LDSM4(qfl[ks][0], qfl[ks][1], qfl[ks][2], qfl[ks][3], sb + FA_SQL + so);
    }

    float oacc[16][4];
#pragma unroll
    for (int nt = 0; nt < 16; ++nt)
#pragma unroll
        for (int e = 0; e < 4; ++e) oacc[nt][e] = 0.f;
    float m0v = -INFINITY, m1v = -INFINITY, l0v = 0.f, l1v = 0.f;

    for (int kb = 0; kb <= qb; ++kb) {
        const int k0 = kb * 64;
        __syncthreads();
#pragma unroll
        for (int i = 0; i < 8; ++i) {
            const int idx = tid + i * 128;
            const int r = idx >> 4;
            const int c = idx & 15;
            cp16(sb + FA_SKH + qsw(r, c), Kb_h + (size_t)(k0 + r) * HEAD_DIM + c * 8);
            cp16(sb + FA_SKL + qsw(r, c), Kb_l + (size_t)(k0 + r) * HEAD_DIM + c * 8);
            const int rv = idx >> 3;
            const int cv = idx & 7;
            cp16(sb + FA_SVH + vsw(rv, cv), Vb_h + (size_t)rv * SEQ + k0 + cv * 8);
        }
        CPC();
        CPW(0);
        __syncthreads();

        float sacc[8][4];
#pragma unroll
        for (int nt = 0; nt < 8; ++nt)
#pragma unroll
            for (int e = 0; e < 4; ++e) sacc[nt][e] = 0.f;

#pragma unroll
        for (int ks = 0; ks < 8; ++ks) {
            const int ch = ks * 2 + (lane >> 4);
            uint32_t bkh[8][2], bkl[8][2];
#pragma unroll
            for (int nt2 = 0; nt2 < 4; ++nt2) {
                const uint32_t so = qsw(nt2 * 16 + (lane & 15), ch);
                uint32_t t0, t1, t2, t3;
                LDSM4(t0, t1, t2, t3, sb + FA_SKH + so);
                bkh[nt2 * 2][0] = t0; bkh[nt2 * 2][1] = t2;
                bkh[nt2 * 2 + 1][0] = t1; bkh[nt2 * 2 + 1][1] = t3;
                LDSM4(t0, t1, t2, t3, sb + FA_SKL + so);
                bkl[nt2 * 2][0] = t0; bkl[nt2 * 2][1] = t2;
                bkl[nt2 * 2 + 1][0] = t1; bkl[nt2 * 2 + 1][1] = t3;
            }
#pragma unroll
            for (int nt = 0; nt < 8; ++nt) {
                mma16816(sacc[nt], qfh[ks], bkh[nt]);
                mma16816(sacc[nt], qfh[ks], bkl[nt]);
                mma16816(sacc[nt], qfl[ks], bkh[nt]);
            }
        }

        const int row0 = q0 + 16 * w + (lane >> 2);
        if (kb == qb) {
#pragma unroll
            for (int nt = 0; nt < 8; ++nt)
#pragma unroll
                for (int e = 0; e < 4; ++e) {
                    const int col = k0 + nt * 8 + (lane & 3) * 2 + (e & 1);
                    const int row = row0 + (e >> 1) * 8;
                    if (col > row) sacc[nt][e] = -INFINITY;
                }
        }

        float rmax0 = -INFINITY, rmax1 = -INFINITY;
#pragma unroll
        for (int nt = 0; nt < 8; ++nt) {
            rmax0 = fmaxf(rmax0, fmaxf(sacc[nt][0], sacc[nt][1]));
            rmax1 = fmaxf(rmax1, fmaxf(sacc[nt][2], sacc[nt][3]));
        }
        rmax0 = fmaxf(rmax0, __shfl_xor_sync(0xffffffffu, rmax0, 1));
        rmax0 = fmaxf(rmax0, __shfl_xor_sync(0xffffffffu, rmax0, 2));
        rmax1 = fmaxf(rmax1, __shfl_xor_sync(0xffffffffu, rmax1, 1));
        rmax1 = fmaxf(rmax1, __shfl_xor_sync(0xffffffffu, rmax1, 2));
        const float mn0 = fmaxf(m0v, rmax0);
        const float mn1 = fmaxf(m1v, rmax1);
        const float al0 = __expf(m0v - mn0);
        const float al1 = __expf(m1v - mn1);
        m0v = mn0; m1v = mn1;
        float rs0 = 0.f, rs1 = 0.f;
#pragma unroll
        for (int nt = 0; nt < 8; ++nt) {
            sacc[nt][0] = __expf(sacc[nt][0] - mn0);
            sacc[nt][1] = __expf(sacc[nt][1] - mn0);
            sacc[nt][2] = __expf(sacc[nt][2] - mn1);
            sacc[nt][3] = __expf(sacc[nt][3] - mn1);
            rs0 += sacc[nt][0] + sacc[nt][1];
            rs1 += sacc[nt][2] + sacc[nt][3];
        }
        rs0 += __shfl_xor_sync(0xffffffffu, rs0, 1);
        rs0 += __shfl_xor_sync(0xffffffffu, rs0, 2);
        rs1 += __shfl_xor_sync(0xffffffffu, rs1, 1);
        rs1 += __shfl_xor_sync(0xffffffffu, rs1, 2);
        l0v = l0v * al0 + rs0;
        l1v = l1v * al1 + rs1;
#pragma unroll
        for (int nt = 0; nt < 16; ++nt) {
            oacc[nt][0] *= al0; oacc[nt][1] *= al0;
            oacc[nt][2] *= al1; oacc[nt][3] *= al1;
        }

        // P fragments, single fp16 (linear path)
        uint32_t pfh[4][4];
#pragma unroll
        for (int kc = 0; kc < 4; ++kc) {
#pragma unroll
            for (int e = 0; e < 4; ++e) {
                const int t  = 2 * kc + (e >> 1);
                const int e0 = (e & 1) * 2;
                const __half2 hv = __floats2half2_rn(sacc[t][e0], sacc[t][e0 + 1]);
                const int slot = ((e >> 1) << 1) | (e & 1);
                pfh[kc][slot] = *(const uint32_t*)&hv;
            }
        }

#pragma unroll
        for (int kc = 0; kc < 4; ++kc) {
#pragma unroll
            for (int g = 0; g < 8; ++g) {
                const uint32_t so = vsw(g * 16 + (lane & 15), kc * 2 + (lane >> 4));
                uint32_t t0, t1, t2, t3;
                uint32_t b0h[2], b1h[2];
                LDSM4(t0, t1, t2, t3, sb + FA_SVH + so);
                b0h[0] = t0; b0h[1] = t2; b1h[0] = t1; b1h[1] = t3;
                mma16816(oacc[2 * g],     pfh[kc], b0h);
                mma16816(oacc[2 * g + 1], pfh[kc], b1h);
            }
        }
    }

    const float inv0 = 1.0f / l0v;
    const float inv1 = 1.0f / l1v;
    const int b = bh >> 4;
    const int h = bh & 15;
    const int row0 = q0 + 16 * w + (lane >> 2);
#pragma unroll
    for (int nt = 0; nt < 16; ++nt) {
        const int col = h * HEAD_DIM + nt * 8 + (lane & 3) * 2;
        const size_t i0 = ((size_t)(b * SEQ + row0)) * D_MODEL + col;
        const size_t i1 = ((size_t)(b * SEQ + row0 + 8)) * D_MODEL + col;
        *(__half2*)&AH[i0] = __floats2half2_rn(oacc[nt][0] * inv0,
                                               oacc[nt][1] * inv0);
        *(__half2*)&AH[i1] = __floats2half2_rn(oacc[nt][2] * inv1,
                                               oacc[nt][3] * inv1);
    }
}

// ---------------------------------------------------------------------------
// Launch
// ---------------------------------------------------------------------------
extern "C" void kernel_launch(void* const* d_in, const int* in_sizes, int n_in,
                              void* d_out, int out_size)
{
    (void)in_sizes; (void)n_in; (void)out_size;
    const float* x  = (const float*)d_in[0];
    const float* wq = (const float*)d_in[1];
    const float* wk = (const float*)d_in[2];
    const float* wv = (const float*)d_in[3];
    const float* wo = (const float*)d_in[4];
    float* out = (float*)d_out;

    __half *xh, *xl, *ah, *wqh, *wkh, *wvh, *woh;
    cudaGetSymbolAddress((void**)&xh, g_x_hi);
    cudaGetSymbolAddress((void**)&xl, g_x_lo);
    cudaGetSymbolAddress((void**)&ah, g_a_hi);
    cudaGetSymbolAddress((void**)&wqh, g_wq_h);
    cudaGetSymbolAddress((void**)&wkh, g_wk_h);
    cudaGetSymbolAddress((void**)&wvh, g_wv_h);
    cudaGetSymbolAddress((void**)&woh, g_wo_h);

    __half *q16h, *q16l, *k16h, *k16l, *v16h, *vt16h;
    cudaGetSymbolAddress((void**)&q16h, g_q16h);
    cudaGetSymbolAddress((void**)&q16l, g_q16l);
    cudaGetSymbolAddress((void**)&k16h, g_k16h);
    cudaGetSymbolAddress((void**)&k16l, g_k16l);
    cudaGetSymbolAddress((void**)&v16h, g_v16h);
    cudaGetSymbolAddress((void**)&vt16h, g_vt16h);

    float *rc, *rs;
    cudaGetSymbolAddress((void**)&rc, g_ropec);
    cudaGetSymbolAddress((void**)&rs, g_ropes);

    const int nx4 = M_ROWS * D_MODEL / 4;
    const int nw4 = D_MODEL * D_MODEL / 4;

    mha_split16<<<nx4 / 256, 256>>>(x, xh, xl, nx4);
    mha_cvt16x4<<<dim3(nw4 / 256, 4), 256>>>(wq, wqh, wk, wkh, wv, wvh, wo, woh,
                                             nw4);
    mha_rope_tables<<<SEQ, 64>>>(rc, rs);

    cudaFuncSetAttribute(gemm_t<0, 1>, cudaFuncAttributeMaxDynamicSharedMemorySize,
                         GSMEM);
    cudaFuncSetAttribute(gemm_t<1, 2>, cudaFuncAttributeMaxDynamicSharedMemorySize,
                         GSMEM);
    cudaFuncSetAttribute(gemm_t<2, 1>, cudaFuncAttributeMaxDynamicSharedMemorySize,
                         GSMEM);
    const dim3 gg(D_MODEL / 128, M_ROWS / 128);

    // Q and K in one launch (blockIdx.x>=16 -> K side)
    gemm_t<1, 2><<<dim3(32, M_ROWS / 128), 128, GSMEM>>>(
        xh, xl, wqh, nullptr, q16h, q16l, 0.08838834764831845f, rc, rs,
        wkh, k16h, k16l, 1.0f);
    gemm_t<2, 1><<<gg, 128, GSMEM>>>(xh, nullptr, wvh, nullptr, v16h, nullptr,
                                     1.0f, rc, rs, nullptr, nullptr, nullptr, 0.f);

    mha_t16<<<dim3(SEQ / 32, HEAD_DIM / 32, BH), dim3(32, 8)>>>(v16h, vt16h);

    cudaFuncSetAttribute(mha_flash_mma, cudaFuncAttributeMaxDynamicSharedMemorySize,
                         FA_SMEM);
    mha_flash_mma<<<dim3(SEQ / 64, BH), 128, FA_SMEM>>>(q16h, q16l, k16h, k16l,
                                                        vt16h, ah);

    gemm_t<0, 1><<<gg, 128, GSMEM>>>(ah, nullptr, woh, out, nullptr, nullptr,
                                     1.0f, rc, rs, nullptr, nullptr, nullptr, 0.f);
}